// round 3
// baseline (speedup 1.0000x reference)
#include <cuda_runtime.h>

#define TM   64     // rows per CTA tile
#define KC   41     // K-chunk of W_edge staged per team (328 = 8*41)
#define NF   656    // feature (GEMM-K) dimension: 16 pos + 640 RBF
#define EC   128    // output columns
#define NTHR 512    // two 256-thread split-K teams

// ---- f32x2 packed-FMA helpers (sm_103a) --------------------------------
__device__ __forceinline__ unsigned long long pack2(float x) {
    unsigned long long r; unsigned u = __float_as_uint(x);
    asm("mov.b64 %0, {%1,%1};" : "=l"(r) : "r"(u));
    return r;
}
__device__ __forceinline__ void ffma2(unsigned long long& d,
                                      unsigned long long a,
                                      unsigned long long b) {
    asm("fma.rn.f32x2 %0, %1, %2, %0;" : "+l"(d) : "l"(a), "l"(b));
}
__device__ __forceinline__ float lo2(unsigned long long v) {
    return __uint_as_float((unsigned)(v & 0xffffffffull));
}
__device__ __forceinline__ float hi2(unsigned long long v) {
    return __uint_as_float((unsigned)(v >> 32));
}
__device__ __forceinline__ void team_bar(int team) {
    asm volatile("bar.sync %0, 256;" :: "r"(1 + team) : "memory");
}

// smem layout (floats): feat[NF*TM] | Wc[2*KC*EC] | dist[TM*41] | smul[TM]
#define SMEM_FLOATS (NF*TM + 2*KC*EC + TM*41 + TM)

__global__ __launch_bounds__(NTHR, 1)
void spf_kernel(const float* __restrict__ X,
                const int*   __restrict__ residue_idx,
                const int*   __restrict__ chain_labels,
                const int*   __restrict__ E_idx,
                const float* __restrict__ W_pos,
                const float* __restrict__ b_pos,
                const float* __restrict__ W_edge,
                const float* __restrict__ ln_gamma,
                const float* __restrict__ ln_beta,
                float*       __restrict__ out,
                int Kn, int A, int nrows, int write_eidx)
{
    extern __shared__ float smem[];
    float* feat = smem;                 // [kk][r] : NF x TM
    float* Wc   = feat + NF * TM;       // 2 teams x [kk][permuted cols] : KC x EC each
    float* dist = Wc + 2 * KC * EC;     // [r][a]  : TM x 41 (padded)
    float* smul = dist + TM * 41;       // self-edge multiplier per row

    const int tid  = threadIdx.x;
    const int row0 = blockIdx.x * TM;

    // ---------------- Phase 1a: distances + positional features ----------
    {
        const int r   = tid >> 3;       // 0..63
        const int sub = tid & 7;        // (a1, half) : 4 bb atoms x 2 halves of 10 sc atoms
        const int a1  = sub >> 1;
        const int h   = sub & 1;
        const int row = row0 + r;
        if (row < nrows) {
            const int i = row / Kn;
            const int j = E_idx[row];
            const int bbm[4] = {1, 0, 2, 3};
            const float* bx = X + ((size_t)i * A + bbm[a1]) * 3;
            const float b0 = bx[0], b1 = bx[1], b2 = bx[2];
            const float* sx = X + ((size_t)j * A + 4 + h * 5) * 3;
            #pragma unroll
            for (int a2 = 0; a2 < 5; a2++) {
                float dx = b0 - sx[a2*3+0];
                float dy = b1 - sx[a2*3+1];
                float dz = b2 - sx[a2*3+2];
                dist[r*41 + a1*10 + h*5 + a2] = sqrtf(dx*dx + dy*dy + dz*dz + 1e-6f);
            }
            if (sub == 0) {
                smul[r] = (j == i) ? 0.0f : 1.0f;
                int off  = residue_idx[i] - residue_idx[j];
                int same = (chain_labels[i] == chain_labels[j]);
                int dpos = same ? min(max(off + 32, 0), 64) : 65;
                #pragma unroll
                for (int c = 0; c < 16; c++)
                    feat[c*TM + r] = W_pos[dpos*16 + c] + b_pos[c];
                if (write_eidx)
                    out[(size_t)nrows * EC + row] = (float)j;
            }
        } else {
            #pragma unroll
            for (int a2 = 0; a2 < 5; a2++) dist[r*41 + a1*10 + h*5 + a2] = 0.0f;
            if (sub == 0) {
                smul[r] = 0.0f;
                #pragma unroll
                for (int c = 0; c < 16; c++) feat[c*TM + r] = 0.0f;
            }
        }
    }
    __syncthreads();

    // ---------------- Phase 1b: RBF features -----------------------------
    #pragma unroll 4
    for (int idx = tid; idx < TM * 640; idx += NTHR) {
        int rr = idx & 63;
        int f  = idx >> 6;              // (a1*10+a2)*16 + m
        float d  = dist[rr*41 + (f >> 4)];
        float mu = 2.0f + (float)(f & 15) * (20.0f / 15.0f);
        float t  = (d - mu) * 0.8f;     // 1/sigma
        feat[(16 + f)*TM + rr] = smul[rr] * __expf(-t * t);
    }
    __syncthreads();

    // ---------------- Phase 2: split-K GEMM, f32x2 packed -----------------
    const int team = tid >> 8;          // 0 or 1 : K halves [0,328) / [328,656)
    const int t256 = tid & 255;
    const int ty   = t256 >> 4;         // 0..15 -> 4 rows each
    const int tx   = t256 & 15;         // 0..15 -> 8 cols each
    float* WcT = Wc + team * (KC * EC);

    unsigned long long acc[4][4];
    #pragma unroll
    for (int i = 0; i < 4; i++)
        #pragma unroll
        for (int j = 0; j < 4; j++) acc[i][j] = 0ull;

    for (int c8 = 0; c8 < 8; c8++) {
        const int chunk = team * 328 + c8 * KC;
        // stage W chunk with even/odd float4-unit permutation:
        // dest slot p <- source unit u = ((p&15)<<1) | (p>>4)
        // => lane loads at word tx*4 later (conflict-free, stride-4 banks)
        for (int idx = t256; idx < KC * 32; idx += 256) {
            int kkr = idx >> 5;
            int pos = idx & 31;
            int u   = ((pos & 15) << 1) | (pos >> 4);
            float4 v = ((const float4*)(W_edge + (size_t)(chunk + kkr) * EC))[u];
            ((float4*)(WcT + kkr * EC))[pos] = v;
        }
        team_bar(team);

        #pragma unroll 4
        for (int kk = 0; kk < KC; kk++) {
            float4 f4 = *(const float4*)&feat[(chunk + kk)*TM + ty*4];
            unsigned long long p0 = pack2(f4.x), p1 = pack2(f4.y),
                               p2 = pack2(f4.z), p3 = pack2(f4.w);
            const float* wrow = WcT + kk*EC;
            ulonglong2 wA = *(const ulonglong2*)(wrow + tx*4);       // cols tx*8+0..3
            ulonglong2 wB = *(const ulonglong2*)(wrow + 64 + tx*4);  // cols tx*8+4..7
            ffma2(acc[0][0], p0, wA.x); ffma2(acc[0][1], p0, wA.y);
            ffma2(acc[0][2], p0, wB.x); ffma2(acc[0][3], p0, wB.y);
            ffma2(acc[1][0], p1, wA.x); ffma2(acc[1][1], p1, wA.y);
            ffma2(acc[1][2], p1, wB.x); ffma2(acc[1][3], p1, wB.y);
            ffma2(acc[2][0], p2, wA.x); ffma2(acc[2][1], p2, wA.y);
            ffma2(acc[2][2], p2, wB.x); ffma2(acc[2][3], p2, wB.y);
            ffma2(acc[3][0], p3, wA.x); ffma2(acc[3][1], p3, wA.y);
            ffma2(acc[3][2], p3, wB.x); ffma2(acc[3][3], p3, wB.y);
        }
        team_bar(team);
    }

    // ---------------- Phase 3: cross-team reduce + LayerNorm --------------
    float* red = Wc;                    // reuse W buffer: 64 x 128 floats
    __syncthreads();                    // all GEMM reads of Wc done
    if (team == 1) {
        #pragma unroll
        for (int ri = 0; ri < 4; ri++) {
            float4 o0, o1;
            o0.x = lo2(acc[ri][0]); o0.y = hi2(acc[ri][0]);
            o0.z = lo2(acc[ri][1]); o0.w = hi2(acc[ri][1]);
            o1.x = lo2(acc[ri][2]); o1.y = hi2(acc[ri][2]);
            o1.z = lo2(acc[ri][3]); o1.w = hi2(acc[ri][3]);
            *(float4*)&red[(ty*4+ri)*EC + tx*8    ] = o0;
            *(float4*)&red[(ty*4+ri)*EC + tx*8 + 4] = o1;
        }
    }
    __syncthreads();

    if (team == 0) {
        float g[8], bb[8];
        #pragma unroll
        for (int c = 0; c < 8; c++) {
            g[c]  = ln_gamma[tx*8 + c];
            bb[c] = ln_beta [tx*8 + c];
        }
        #pragma unroll
        for (int ri = 0; ri < 4; ri++) {
            float v[8];
            #pragma unroll
            for (int ci = 0; ci < 4; ci++) {
                v[2*ci]   = lo2(acc[ri][ci]);
                v[2*ci+1] = hi2(acc[ri][ci]);
            }
            const float* rrow = &red[(ty*4+ri)*EC + tx*8];
            #pragma unroll
            for (int c = 0; c < 8; c++) v[c] += rrow[c];

            float s = 0.0f;
            #pragma unroll
            for (int c = 0; c < 8; c++) s += v[c];
            #pragma unroll
            for (int o = 8; o >= 1; o >>= 1)
                s += __shfl_xor_sync(0xffffffffu, s, o, 16);
            float mean = s * (1.0f / 128.0f);

            float q = 0.0f;
            #pragma unroll
            for (int c = 0; c < 8; c++) { float d = v[c] - mean; q += d * d; }
            #pragma unroll
            for (int o = 8; o >= 1; o >>= 1)
                q += __shfl_xor_sync(0xffffffffu, q, o, 16);
            float rstd = rsqrtf(q * (1.0f / 128.0f) + 1e-5f);

            int row = row0 + ty*4 + ri;
            if (row < nrows) {
                float4 o0, o1;
                o0.x = (v[0]-mean)*rstd*g[0] + bb[0];
                o0.y = (v[1]-mean)*rstd*g[1] + bb[1];
                o0.z = (v[2]-mean)*rstd*g[2] + bb[2];
                o0.w = (v[3]-mean)*rstd*g[3] + bb[3];
                o1.x = (v[4]-mean)*rstd*g[4] + bb[4];
                o1.y = (v[5]-mean)*rstd*g[5] + bb[5];
                o1.z = (v[6]-mean)*rstd*g[6] + bb[6];
                o1.w = (v[7]-mean)*rstd*g[7] + bb[7];
                *(float4*)&out[(size_t)row*EC + tx*8    ] = o0;
                *(float4*)&out[(size_t)row*EC + tx*8 + 4] = o1;
            }
        }
    }
}

extern "C" void kernel_launch(void* const* d_in, const int* in_sizes, int n_in,
                              void* d_out, int out_size)
{
    const float* X           = (const float*)d_in[0];
    const int*   residue_idx = (const int*)  d_in[1];
    const int*   chain_lab   = (const int*)  d_in[2];
    const int*   E_idx       = (const int*)  d_in[3];
    // d_in[4] = atom_mask (unused by reference)
    const float* W_pos       = (const float*)d_in[5];
    const float* b_pos       = (const float*)d_in[6];
    const float* W_edge      = (const float*)d_in[7];
    const float* ln_gamma    = (const float*)d_in[8];
    const float* ln_beta     = (const float*)d_in[9];
    float*       out         = (float*)d_out;

    const int BL    = in_sizes[1];            // B*L
    const int nrows = in_sizes[3];            // B*L*K
    const int Kn    = nrows / BL;             // K
    const int A     = in_sizes[0] / (BL * 3); // 14
    const int write_eidx = (out_size >= nrows * (EC + 1)) ? 1 : 0;

    const int grid = (nrows + TM - 1) / TM;
    const size_t shb = (size_t)SMEM_FLOATS * sizeof(float);

    cudaFuncSetAttribute(spf_kernel,
                         cudaFuncAttributeMaxDynamicSharedMemorySize, (int)shb);

    spf_kernel<<<grid, NTHR, shb>>>(X, residue_idx, chain_lab, E_idx,
                                    W_pos, b_pos, W_edge, ln_gamma, ln_beta,
                                    out, Kn, A, nrows, write_eidx);
}

// round 4
// speedup vs baseline: 1.8282x; 1.8282x over previous
#include <cuda_runtime.h>

#define TM   128    // rows per CTA
#define KC   41     // K-chunk (656 = 16*41)
#define NCH  16
#define NF   656
#define EC   128
#define NTHR 256

// ---- f32x2 packed-FMA helpers (sm_103a) --------------------------------
__device__ __forceinline__ unsigned long long pack2(float x) {
    unsigned long long r; unsigned u = __float_as_uint(x);
    asm("mov.b64 %0, {%1,%1};" : "=l"(r) : "r"(u));
    return r;
}
__device__ __forceinline__ void ffma2(unsigned long long& d,
                                      unsigned long long a,
                                      unsigned long long b) {
    asm("fma.rn.f32x2 %0, %1, %2, %0;" : "+l"(d) : "l"(a), "l"(b));
}
__device__ __forceinline__ float lo2(unsigned long long v) {
    return __uint_as_float((unsigned)(v & 0xffffffffull));
}
__device__ __forceinline__ float hi2(unsigned long long v) {
    return __uint_as_float((unsigned)(v >> 32));
}
__device__ __forceinline__ void cp_async16(unsigned dst_smem, const void* src) {
    asm volatile("cp.async.cg.shared.global [%0], [%1], 16;"
                 :: "r"(dst_smem), "l"(src) : "memory");
}

// smem floats: Wbuf[2][KC*EC] | featbuf[2][KC*TM] | dist[TM*41] | smul[TM] | dpos[TM]
#define CHW   (KC*EC)            // 5248
#define CHF   (KC*TM)            // 5248
#define SMEM_FLOATS (2*CHW + 2*CHF + TM*41 + TM + TM)

__global__ __launch_bounds__(NTHR, 2)
void spf_kernel(const float* __restrict__ X,
                const int*   __restrict__ residue_idx,
                const int*   __restrict__ chain_labels,
                const int*   __restrict__ E_idx,
                const float* __restrict__ W_pos,
                const float* __restrict__ b_pos,
                const float* __restrict__ W_edge,
                const float* __restrict__ ln_gamma,
                const float* __restrict__ ln_beta,
                float*       __restrict__ out,
                int Kn, int A, int nrows, int write_eidx)
{
    extern __shared__ float smem[];
    float* Wbuf  = smem;                       // 2 x KC x EC (bank-permuted)
    float* fbuf  = Wbuf + 2*CHW;               // 2 x KC x TM ([kk][r])
    float* dist  = fbuf + 2*CHF;               // [r][a] TM x 41
    float* smul  = dist + TM*41;
    int*   dposs = (int*)(smul + TM);

    const int tid  = threadIdx.x;
    const int row0 = blockIdx.x * TM;

    // ---------------- Phase 1a: distances, smul, dpos ---------------------
    {
        const int r    = tid >> 1;             // 0..127
        const int half = tid & 1;              // bb atoms {0,1} or {2,3}
        const int row  = row0 + r;
        if (row < nrows) {
            const int i = row / Kn;
            const int j = E_idx[row];
            const int bbm[4] = {1, 0, 2, 3};
            const float* sx = X + ((size_t)j * A + 4) * 3;
            float s[30];
            #pragma unroll
            for (int q = 0; q < 30; q++) s[q] = sx[q];
            #pragma unroll
            for (int aa = 0; aa < 2; aa++) {
                const int a1 = half*2 + aa;
                const float* bx = X + ((size_t)i * A + bbm[a1]) * 3;
                const float b0 = bx[0], b1 = bx[1], b2 = bx[2];
                #pragma unroll
                for (int a2 = 0; a2 < 10; a2++) {
                    float dx = b0 - s[a2*3+0];
                    float dy = b1 - s[a2*3+1];
                    float dz = b2 - s[a2*3+2];
                    dist[r*41 + a1*10 + a2] = sqrtf(dx*dx + dy*dy + dz*dz + 1e-6f);
                }
            }
            if (half == 0) {
                smul[r] = (j == i) ? 0.0f : 1.0f;
                int off  = residue_idx[i] - residue_idx[j];
                int same = (chain_labels[i] == chain_labels[j]);
                dposs[r] = same ? min(max(off + 32, 0), 64) : 65;
                if (write_eidx)
                    out[(size_t)nrows * EC + row] = (float)j;
            }
        } else {
            #pragma unroll
            for (int aa = 0; aa < 2; aa++)
                #pragma unroll
                for (int a2 = 0; a2 < 10; a2++)
                    dist[r*41 + (half*2+aa)*10 + a2] = 0.0f;
            if (half == 0) { smul[r] = 0.0f; dposs[r] = 0; }
        }
    }
    __syncthreads();

    // ---------------- staging lambdas -------------------------------------
    const unsigned smem_base = (unsigned)__cvta_generic_to_shared(smem);

    auto stage_W = [&](int c, int buf) {
        // 16B granule permutation: dst slot p <- src unit u, p = ((u&1)<<4)|(u>>1)
        // => GEMM lane reads at word tx*4 / 64+tx*4: conflict-free
        const int k0 = c * KC;
        const unsigned wb = smem_base + (unsigned)((buf*CHW) * 4);
        for (int g = tid; g < KC*32; g += NTHR) {
            int kkr = g >> 5;
            int u   = g & 31;
            int p   = ((u & 1) << 4) | (u >> 1);
            cp_async16(wb + (unsigned)((kkr*EC + p*4) * 4),
                       W_edge + (size_t)(k0 + kkr) * EC + u*4);
        }
    };

    auto stage_feat = [&](int c, int buf) {
        const int k0 = c * KC;
        float* fb = fbuf + buf*CHF;
        for (int idx = tid; idx < CHF; idx += NTHR) {
            int kk = idx >> 7;                 // TM=128
            int r  = idx & 127;
            int k  = k0 + kk;
            float v;
            if (k < 16) {
                v = W_pos[dposs[r]*16 + k] + b_pos[k];
            } else {
                int f = k - 16;
                float d  = dist[r*41 + (f >> 4)];
                float mu = 2.0f + (float)(f & 15) * (20.0f / 15.0f);
                float t  = (d - mu) * 0.8f;
                v = smul[r] * __expf(-t * t);
            }
            fb[kk*TM + r] = v;
        }
    };

    // ---------------- Phase 2: GEMM with double-buffered chunks -----------
    const int ty = tid >> 4;                   // 0..15 -> 8 rows each
    const int tx = tid & 15;                   // 0..15 -> 8 cols each

    unsigned long long acc[8][4];
    #pragma unroll
    for (int i = 0; i < 8; i++)
        #pragma unroll
        for (int j = 0; j < 4; j++) acc[i][j] = 0ull;

    // prologue: fill buffer 0
    stage_W(0, 0);
    asm volatile("cp.async.commit_group;" ::: "memory");
    stage_feat(0, 0);
    asm volatile("cp.async.wait_group 0;" ::: "memory");
    __syncthreads();

    int cur = 0;
    for (int c = 0; c < NCH; c++) {
        const int nxt = cur ^ 1;
        if (c + 1 < NCH) {
            stage_W(c + 1, nxt);
            asm volatile("cp.async.commit_group;" ::: "memory");
            stage_feat(c + 1, nxt);
        }

        const float* fb = fbuf + cur*CHF;
        const float* wb = Wbuf + cur*CHW;
        #pragma unroll 4
        for (int kk = 0; kk < KC; kk++) {
            float4 fa = *(const float4*)&fb[kk*TM + ty*8];
            float4 fc = *(const float4*)&fb[kk*TM + ty*8 + 4];
            const float* wrow = wb + kk*EC;
            ulonglong2 wA = *(const ulonglong2*)(wrow + tx*4);      // cols 8tx..+3
            ulonglong2 wB = *(const ulonglong2*)(wrow + 64 + tx*4); // cols 8tx+4..+7
            unsigned long long p0 = pack2(fa.x), p1 = pack2(fa.y),
                               p2 = pack2(fa.z), p3 = pack2(fa.w),
                               p4 = pack2(fc.x), p5 = pack2(fc.y),
                               p6 = pack2(fc.z), p7 = pack2(fc.w);
            ffma2(acc[0][0], p0, wA.x); ffma2(acc[0][1], p0, wA.y);
            ffma2(acc[0][2], p0, wB.x); ffma2(acc[0][3], p0, wB.y);
            ffma2(acc[1][0], p1, wA.x); ffma2(acc[1][1], p1, wA.y);
            ffma2(acc[1][2], p1, wB.x); ffma2(acc[1][3], p1, wB.y);
            ffma2(acc[2][0], p2, wA.x); ffma2(acc[2][1], p2, wA.y);
            ffma2(acc[2][2], p2, wB.x); ffma2(acc[2][3], p2, wB.y);
            ffma2(acc[3][0], p3, wA.x); ffma2(acc[3][1], p3, wA.y);
            ffma2(acc[3][2], p3, wB.x); ffma2(acc[3][3], p3, wB.y);
            ffma2(acc[4][0], p4, wA.x); ffma2(acc[4][1], p4, wA.y);
            ffma2(acc[4][2], p4, wB.x); ffma2(acc[4][3], p4, wB.y);
            ffma2(acc[5][0], p5, wA.x); ffma2(acc[5][1], p5, wA.y);
            ffma2(acc[5][2], p5, wB.x); ffma2(acc[5][3], p5, wB.y);
            ffma2(acc[6][0], p6, wA.x); ffma2(acc[6][1], p6, wA.y);
            ffma2(acc[6][2], p6, wB.x); ffma2(acc[6][3], p6, wB.y);
            ffma2(acc[7][0], p7, wA.x); ffma2(acc[7][1], p7, wA.y);
            ffma2(acc[7][2], p7, wB.x); ffma2(acc[7][3], p7, wB.y);
        }

        if (c + 1 < NCH)
            asm volatile("cp.async.wait_group 0;" ::: "memory");
        __syncthreads();
        cur = nxt;
    }

    // ---------------- Phase 3: LayerNorm + store --------------------------
    float g[8], bb[8];
    #pragma unroll
    for (int cc = 0; cc < 8; cc++) {
        g[cc]  = ln_gamma[tx*8 + cc];
        bb[cc] = ln_beta [tx*8 + cc];
    }

    #pragma unroll
    for (int ri = 0; ri < 8; ri++) {
        float v[8];
        #pragma unroll
        for (int ci = 0; ci < 4; ci++) {
            v[2*ci]   = lo2(acc[ri][ci]);
            v[2*ci+1] = hi2(acc[ri][ci]);
        }
        float s = 0.0f;
        #pragma unroll
        for (int cc = 0; cc < 8; cc++) s += v[cc];
        #pragma unroll
        for (int o = 8; o >= 1; o >>= 1)
            s += __shfl_xor_sync(0xffffffffu, s, o, 16);
        float mean = s * (1.0f / 128.0f);

        float q = 0.0f;
        #pragma unroll
        for (int cc = 0; cc < 8; cc++) { float d = v[cc] - mean; q += d * d; }
        #pragma unroll
        for (int o = 8; o >= 1; o >>= 1)
            q += __shfl_xor_sync(0xffffffffu, q, o, 16);
        float rstd = rsqrtf(q * (1.0f / 128.0f) + 1e-5f);

        int row = row0 + ty*8 + ri;
        if (row < nrows) {
            float4 o0, o1;
            o0.x = (v[0]-mean)*rstd*g[0] + bb[0];
            o0.y = (v[1]-mean)*rstd*g[1] + bb[1];
            o0.z = (v[2]-mean)*rstd*g[2] + bb[2];
            o0.w = (v[3]-mean)*rstd*g[3] + bb[3];
            o1.x = (v[4]-mean)*rstd*g[4] + bb[4];
            o1.y = (v[5]-mean)*rstd*g[5] + bb[5];
            o1.z = (v[6]-mean)*rstd*g[6] + bb[6];
            o1.w = (v[7]-mean)*rstd*g[7] + bb[7];
            *(float4*)&out[(size_t)row*EC + tx*8    ] = o0;
            *(float4*)&out[(size_t)row*EC + tx*8 + 4] = o1;
        }
    }
}

extern "C" void kernel_launch(void* const* d_in, const int* in_sizes, int n_in,
                              void* d_out, int out_size)
{
    const float* X           = (const float*)d_in[0];
    const int*   residue_idx = (const int*)  d_in[1];
    const int*   chain_lab   = (const int*)  d_in[2];
    const int*   E_idx       = (const int*)  d_in[3];
    // d_in[4] = atom_mask (unused by reference)
    const float* W_pos       = (const float*)d_in[5];
    const float* b_pos       = (const float*)d_in[6];
    const float* W_edge      = (const float*)d_in[7];
    const float* ln_gamma    = (const float*)d_in[8];
    const float* ln_beta     = (const float*)d_in[9];
    float*       out         = (float*)d_out;

    const int BL    = in_sizes[1];            // B*L
    const int nrows = in_sizes[3];            // B*L*K
    const int Kn    = nrows / BL;             // K
    const int A     = in_sizes[0] / (BL * 3); // 14
    const int write_eidx = (out_size >= nrows * (EC + 1)) ? 1 : 0;

    const int grid = (nrows + TM - 1) / TM;
    const size_t shb = (size_t)SMEM_FLOATS * sizeof(float);

    cudaFuncSetAttribute(spf_kernel,
                         cudaFuncAttributeMaxDynamicSharedMemorySize, (int)shb);

    spf_kernel<<<grid, NTHR, shb>>>(X, residue_idx, chain_lab, E_idx,
                                    W_pos, b_pos, W_edge, ln_gamma, ln_beta,
                                    out, Kn, A, nrows, write_eidx);
}